// round 14
// baseline (speedup 1.0000x reference)
#include <cuda_runtime.h>
#include <cuda_bf16.h>
#include <cuda_fp16.h>
#include <cstdint>

#define B_    512
#define N_    50
#define D_    128
#define H_    200
#define E_    50000
#define EPAD  50048         // 391*128 — padded entity rows (zero-init tail)
#define KPAD  208           // H_ padded to 13*16 for decoder mma
#define GBM   128
#define GBN   128
#define NPART 391           // EPAD/GBN
#define SAS   216           // decoder gemm smem stride (bf16 elems)
#define PSTR  136           // projection gemm smem stride (bf16)
#define RHALF 256           // batch rows per pipeline half

// ---------------- static device scratch ----------------
__device__ __nv_bfloat16 g_wb[(size_t)EPAD * KPAD];    // mlp_w bf16, padded (tail zero)
__device__ __align__(16) __half g_sc[(size_t)B_ * E_]; // fp16 exp(score) (51.2 MB)
__device__ __align__(16) float g_x[(size_t)B_ * N_ * H_]; // projected x (20.5 MB)
__device__ __nv_bfloat16 g_vb[B_ * KPAD];              // poses bf16, K-padded
__device__ float g_v[B_ * H_];                         // poses fp32 (for fixdot)
__device__ float g_part[(size_t)B_ * NPART];           // per-(row, e-block) exp partials
__device__ float g_invZs[B_];                          // 0.5 / Z_s
__device__ float g_pbase[B_];                          // 0.5 * exp(-m_p) / Z_p
__device__ float g_fix_p[B_ * N_];
__device__ int   g_fix_id[B_ * N_];
__device__ int   g_fix_cnt[B_];

// ---------------- shared PTX helpers ----------------
__device__ __forceinline__ uint32_t smem_u32(const void* p) {
    uint32_t a;
    asm("{ .reg .u64 t; cvta.to.shared.u64 t, %1; cvt.u32.u64 %0, t; }" : "=r"(a) : "l"(p));
    return a;
}
__device__ __forceinline__ void mma16816(float* c, const unsigned* a, const unsigned* b) {
    asm volatile("mma.sync.aligned.m16n8k16.row.col.f32.bf16.bf16.f32 "
        "{%0,%1,%2,%3}, {%4,%5,%6,%7}, {%8,%9}, {%0,%1,%2,%3};"
        : "+f"(c[0]), "+f"(c[1]), "+f"(c[2]), "+f"(c[3])
        : "r"(a[0]), "r"(a[1]), "r"(a[2]), "r"(a[3]), "r"(b[0]), "r"(b[1]));
}
__device__ __forceinline__ void ldsm_x4(unsigned* r, uint32_t addr) {
    asm volatile("ldmatrix.sync.aligned.m8n8.x4.shared.b16 {%0,%1,%2,%3}, [%4];"
        : "=r"(r[0]), "=r"(r[1]), "=r"(r[2]), "=r"(r[3]) : "r"(addr));
}
__device__ __forceinline__ void cp16(uint32_t dst, const void* src) {
    asm volatile("cp.async.cg.shared.global [%0], [%1], 16;" :: "r"(dst), "l"(src));
}
#define CP_COMMIT() asm volatile("cp.async.commit_group;")
#define CP_WAIT0()  asm volatile("cp.async.wait_group 0;" ::: "memory")

// ---------------- K0: mlp_w fp32 -> bf16 padded ----------------
__global__ void k_convert(const float* __restrict__ w) {
    int i = blockIdx.x * 256 + threadIdx.x;        // uint2 (4 bf16) index
    if (i >= E_ * 52) return;
    int e = i / 52, q = i % 52;
    uint2 val;
    if (q < 50) {
        float4 f = *(const float4*)(w + (size_t)e * H_ + 4 * q);
        __nv_bfloat162 lo = __floats2bfloat162_rn(f.x, f.y);
        __nv_bfloat162 hi = __floats2bfloat162_rn(f.z, f.w);
        val.x = *(unsigned*)&lo;
        val.y = *(unsigned*)&hi;
    } else {
        val.x = 0u; val.y = 0u;
    }
    ((uint2*)g_wb)[(size_t)e * 52 + q] = val;
}

// ---------------- K-proj: X = gather(embeds) @ Ws^T + b   (bf16 mma) ----------------
#define PROJ_SMEM ((128 * PSTR + 224 * PSTR) * 2 + 224 * 4)

__global__ void __launch_bounds__(512) k_proj(
    const int* __restrict__ idx, const float* __restrict__ emb,
    const float* __restrict__ Ws_w, const float* __restrict__ Ws_b)
{
    extern __shared__ __align__(16) char psm[];
    __nv_bfloat16* sA = (__nv_bfloat16*)psm;          // [128][PSTR]
    __nv_bfloat16* sB = sA + 128 * PSTR;              // [224][PSTR]
    float* sBias = (float*)(sB + 224 * PSTR);         // [224]

    const int tid = threadIdx.x;
    const int m0 = blockIdx.x * 128;

    if (tid < 224) sBias[tid] = (tid < H_) ? Ws_b[tid] : 0.f;
    for (int i = tid; i < 128 * 32; i += 512) {
        int r = i >> 5, c4 = i & 31;
        int e = idx[m0 + r];
        float4 f = *(const float4*)(emb + (size_t)e * D_ + 4 * c4);
        __nv_bfloat162 lo = __floats2bfloat162_rn(f.x, f.y);
        __nv_bfloat162 hi = __floats2bfloat162_rn(f.z, f.w);
        uint2 v; v.x = *(unsigned*)&lo; v.y = *(unsigned*)&hi;
        ((uint2*)(sA + r * PSTR))[c4] = v;
    }
    for (int i = tid; i < 200 * 32; i += 512) {
        int r = i >> 5, c4 = i & 31;
        float4 f = *(const float4*)(Ws_w + r * D_ + 4 * c4);
        __nv_bfloat162 lo = __floats2bfloat162_rn(f.x, f.y);
        __nv_bfloat162 hi = __floats2bfloat162_rn(f.z, f.w);
        uint2 v; v.x = *(unsigned*)&lo; v.y = *(unsigned*)&hi;
        ((uint2*)(sB + r * PSTR))[c4] = v;
    }
    __syncthreads();

    const int lane = tid & 31, warp = tid >> 5;
    const int gid = lane >> 2, tig = lane & 3;
    const int wm = warp & 7, wn = warp >> 3;

    const uint32_t sA_u = smem_u32(sA), sB_u = smem_u32(sB);
    const uint32_t aAddr = sA_u + (uint32_t)(((wm * 16 + (lane & 15)) * PSTR + (lane >> 4) * 8) * 2);
    uint32_t bAddr[7];
#pragma unroll
    for (int j = 0; j < 7; j++)
        bAddr[j] = sB_u + (uint32_t)(((wn * 112 + j * 16 + (lane & 7) + ((lane >> 4) & 1) * 8) * PSTR
                                     + ((lane >> 3) & 1) * 8) * 2);

    float acc[14][4];
#pragma unroll
    for (int ni = 0; ni < 14; ni++)
#pragma unroll
        for (int q = 0; q < 4; q++) acc[ni][q] = 0.f;

#pragma unroll
    for (int ks = 0; ks < 8; ks++) {
        const uint32_t koff = ks * 32u;
        unsigned a[4];
        ldsm_x4(a, aAddr + koff);
#pragma unroll
        for (int j = 0; j < 7; j++) {
            unsigned bb[4];
            ldsm_x4(bb, bAddr[j] + koff);
            mma16816(acc[2 * j],     a, bb + 0);
            mma16816(acc[2 * j + 1], a, bb + 2);
        }
    }

    const int r0 = m0 + wm * 16 + gid;
#pragma unroll
    for (int ni = 0; ni < 14; ni++) {
        int c = wn * 112 + ni * 8 + 2 * tig;
        if (c < H_) {
            float b0 = sBias[c], b1 = sBias[c + 1];
            float2 v0, v1;
            v0.x = acc[ni][0] + b0; v0.y = acc[ni][1] + b1;
            v1.x = acc[ni][2] + b0; v1.y = acc[ni][3] + b1;
            *(float2*)(g_x + (size_t)r0 * H_ + c)       = v0;
            *(float2*)(g_x + (size_t)(r0 + 8) * H_ + c) = v1;
        }
    }
}

// ---------------- K1: routing (256 thr, fused gather+normalize) ----------------
__global__ void __launch_bounds__(256, 4) k_routing(
    const int* __restrict__ idx, const int* __restrict__ times)
{
    __shared__ __align__(16) float sU[50 * 200];
    __shared__ float sB[50], sC[50], sV[200], sTmp[50], sRed[8];
    __shared__ int   sIdx[50];

    const int tid = threadIdx.x;
    const int lane = tid & 31, wid = tid >> 5;   // 8 warps
    const int row = blockIdx.x;

    if (tid < 50) {
        sIdx[tid] = idx[row * N_ + tid];
        sB[tid] = 2.0f / (1.0f + (float)times[row * N_ + tid]);
    }

    for (int n = wid; n < 50; n += 8) {
        const float4* src = (const float4*)(g_x + ((size_t)row * N_ + n) * H_);
        float4 f0 = src[lane];
        float ss = f0.x * f0.x + f0.y * f0.y + f0.z * f0.z + f0.w * f0.w;
        float4 f1;
        const bool has2 = lane < 18;
        if (has2) {
            f1 = src[32 + lane];
            ss += f1.x * f1.x + f1.y * f1.y + f1.z * f1.z + f1.w * f1.w;
        }
#pragma unroll
        for (int o = 16; o > 0; o >>= 1) ss += __shfl_xor_sync(0xffffffffu, ss, o);
        float inv = 1.0f / fmaxf(sqrtf(ss), 1e-12f);
        float4* dst = (float4*)(sU + n * 200);
        f0.x *= inv; f0.y *= inv; f0.z *= inv; f0.w *= inv;
        dst[lane] = f0;
        if (has2) {
            f1.x *= inv; f1.y *= inv; f1.z *= inv; f1.w *= inv;
            dst[32 + lane] = f1;
        }
    }
    __syncthreads();

    for (int r = 0; r < 3; r++) {
        if (wid == 0) {
            float v0 = (lane < 50) ? sB[lane] : -1e30f;
            float v1 = (lane + 32 < 50) ? sB[lane + 32] : -1e30f;
            float m = fmaxf(v0, v1);
#pragma unroll
            for (int o = 16; o > 0; o >>= 1) m = fmaxf(m, __shfl_xor_sync(0xffffffffu, m, o));
            float e0 = (lane < 50) ? expf(v0 - m) : 0.f;
            float e1 = (lane + 32 < 50) ? expf(v1 - m) : 0.f;
            float s = e0 + e1;
#pragma unroll
            for (int o = 16; o > 0; o >>= 1) s += __shfl_xor_sync(0xffffffffu, s, o);
            float sc = 50.0f / s;
            if (lane < 50) sC[lane] = e0 * sc;
            if (lane + 32 < 50) sC[lane + 32] = e1 * sc;
        }
        __syncthreads();

        float sv = 0.f, mysq = 0.f;
        if (tid < H_) {
#pragma unroll 5
            for (int n = 0; n < 50; n++) sv += sC[n] * sU[n * H_ + tid];
            mysq = sv * sv;
        }
#pragma unroll
        for (int o = 16; o > 0; o >>= 1) mysq += __shfl_xor_sync(0xffffffffu, mysq, o);
        if (lane == 0) sRed[wid] = mysq;
        __syncthreads();

        float sq = 0.f;
#pragma unroll
        for (int i = 0; i < 8; i++) sq += sRed[i];
        float scale = sq / ((1.0f + sq) * sqrtf(sq + 1e-9f));
        if (tid < H_) sV[tid] = sv * scale;
        __syncthreads();

        if (r < 2) {
            for (int n = wid; n < 50; n += 8) {
                float dot = 0.f;
                for (int h = lane; h < H_; h += 32) dot += sU[n * H_ + h] * sV[h];
#pragma unroll
                for (int o = 16; o > 0; o >>= 1) dot += __shfl_xor_sync(0xffffffffu, dot, o);
                if (lane == 0) sB[n] += dot;
            }
            __syncthreads();
        }
    }

    if (tid < H_) {
        float v = sV[tid];
        g_v[row * H_ + tid] = v;
        g_vb[row * KPAD + tid] = __float2bfloat16(v);
    } else if (tid < KPAD) {
        g_vb[row * KPAD + tid] = __float2bfloat16(0.f);
    }

    if (tid < 50) {
        int my = sIdx[tid];
        bool first = true;
        float cs = 0.f;
        for (int m = 0; m < 50; m++) {
            if (sIdx[m] == my) {
                cs += sC[m];
                if (m < tid) first = false;
            }
        }
        sTmp[tid] = first ? cs : -1.0f;
    }
    __syncthreads();
    if (tid == 0) {
        float mp = -1e30f; int K = 0;
        for (int n = 0; n < 50; n++)
            if (sTmp[n] >= 0.f) { K++; mp = fmaxf(mp, sTmp[n]); }
        float Zp = (float)(E_ - K) * expf(-mp);
        for (int n = 0; n < 50; n++)
            if (sTmp[n] >= 0.f) Zp += expf(sTmp[n] - mp);
        int slot = 0;
        for (int n = 0; n < 50; n++)
            if (sTmp[n] >= 0.f) {
                g_fix_id[row * N_ + slot] = sIdx[n];
                g_fix_p[row * N_ + slot] = 0.5f * expf(sTmp[n] - mp) / Zp;
                slot++;
            }
        g_fix_cnt[row] = K;
        g_pbase[row] = 0.5f * expf(-mp) / Zp;
    }
}

// ---------------- K2: decoder GEMM 128x128 (half-batch, rOff) ----------------
#define GEMM_DSMEM ((GBM + GBN) * SAS * 2 + 512)

__global__ void __launch_bounds__(512) k_gemm(const float* __restrict__ mlp_b, int rOff)
{
    extern __shared__ __align__(16) char gsm[];
    __nv_bfloat16* sA   = (__nv_bfloat16*)gsm;
    __nv_bfloat16* sBm  = sA + GBM * SAS;
    float*         sBias= (float*)(sBm + GBN * SAS);
    float (*s_part)[16] = (float (*)[16])gsm;

    const int tid = threadIdx.x;
    const int rBase = rOff + blockIdx.x * GBM;   // 2 r-tiles fastest
    const int eBase = blockIdx.y * GBN;

    if (tid < GBN) {
        int e = eBase + tid;
        sBias[tid] = (e < E_) ? mlp_b[e] : 0.f;
    }
    {
        const uint32_t sA_b = smem_u32(sA), sB_b = smem_u32(sBm);
        const char* srcA = (const char*)g_vb + (size_t)rBase * KPAD * 2;
        const char* srcB = (const char*)g_wb + (size_t)eBase * KPAD * 2;
        for (int i = tid; i < GBM * 26; i += 512) {
            int r = i / 26, c = i - r * 26;
            cp16(sA_b + (uint32_t)(r * (SAS * 2) + c * 16), srcA + (size_t)r * 416 + c * 16);
        }
        for (int i = tid; i < GBN * 26; i += 512) {
            int r = i / 26, c = i - r * 26;
            cp16(sB_b + (uint32_t)(r * (SAS * 2) + c * 16), srcB + (size_t)r * 416 + c * 16);
        }
        CP_COMMIT();
        CP_WAIT0();
    }
    __syncthreads();

    const int lane = tid & 31, warp = tid >> 5;
    const int gid = lane >> 2, tig = lane & 3;
    const int wm = warp & 3, wn = warp >> 2;

    const uint32_t sA_u = smem_u32(sA), sB_u = smem_u32(sBm);
    uint32_t aAddr0 = sA_u + (uint32_t)(((wm * 32 + (lane & 15)) * SAS + ((lane >> 4) * 8)) * 2);
    uint32_t aAddr1 = aAddr0 + 16u * SAS * 2u;
    uint32_t bAddr0 = sB_u + (uint32_t)(((wn * 32 + (lane & 7) + (((lane >> 4) & 1) * 8)) * SAS
                                        + (((lane >> 3) & 1) * 8)) * 2);
    uint32_t bAddr1 = bAddr0 + 16u * SAS * 2u;

    float acc[2][4][4];
#pragma unroll
    for (int mi = 0; mi < 2; mi++)
#pragma unroll
        for (int ni = 0; ni < 4; ni++)
#pragma unroll
            for (int q = 0; q < 4; q++) acc[mi][ni][q] = 0.f;

#pragma unroll
    for (int ks = 0; ks < 13; ks++) {
        const uint32_t koff = ks * 32u;
        unsigned a0[4], a1[4], b0[4], b1[4];
        ldsm_x4(a0, aAddr0 + koff);
        ldsm_x4(a1, aAddr1 + koff);
        ldsm_x4(b0, bAddr0 + koff);
        ldsm_x4(b1, bAddr1 + koff);
        mma16816(acc[0][0], a0, b0 + 0);
        mma16816(acc[0][1], a0, b0 + 2);
        mma16816(acc[0][2], a0, b1 + 0);
        mma16816(acc[0][3], a0, b1 + 2);
        mma16816(acc[1][0], a1, b0 + 0);
        mma16816(acc[1][1], a1, b0 + 2);
        mma16816(acc[1][2], a1, b1 + 0);
        mma16816(acc[1][3], a1, b1 + 2);
    }

    float rs[2][2] = {{0.f, 0.f}, {0.f, 0.f}};
#pragma unroll
    for (int mi = 0; mi < 2; mi++) {
        int r0 = rBase + wm * 32 + mi * 16 + gid;
#pragma unroll
        for (int ni = 0; ni < 4; ni++) {
            int ec = wn * 32 + ni * 8 + 2 * tig;
            int e0 = eBase + ec;
            if (e0 < E_) {
                float b0 = sBias[ec], b1 = sBias[ec + 1];
                float E00 = __expf(acc[mi][ni][0] + b0);
                float E01 = __expf(acc[mi][ni][1] + b1);
                float E10 = __expf(acc[mi][ni][2] + b0);
                float E11 = __expf(acc[mi][ni][3] + b1);
                *(__half2*)(g_sc + (size_t)r0 * E_ + e0)       = __floats2half2_rn(E00, E01);
                *(__half2*)(g_sc + (size_t)(r0 + 8) * E_ + e0) = __floats2half2_rn(E10, E11);
                rs[mi][0] += E00 + E01;
                rs[mi][1] += E10 + E11;
            }
        }
    }
    __syncthreads();   // sA dead -> safe to alias as s_part
    const int slot = wn * 4 + tig;
#pragma unroll
    for (int mi = 0; mi < 2; mi++) {
        s_part[wm * 32 + mi * 16 + gid][slot]     = rs[mi][0];
        s_part[wm * 32 + mi * 16 + gid + 8][slot] = rs[mi][1];
    }
    __syncthreads();
    if (tid < GBM) {
        float s = 0.f;
#pragma unroll
        for (int j = 0; j < 16; j++) s += s_part[tid][j];
        g_part[(size_t)(rBase + tid) * NPART + blockIdx.y] = s;
    }
}

// ---------------- K3: fused reduce (0.5/Z_s) + fixdot (block per row) ----------------
__global__ void __launch_bounds__(256) k_reducefix(const float* __restrict__ mlp_w,
                                                   const float* __restrict__ mlp_b, int rOff) {
    __shared__ float red[256];
    __shared__ float s_iz[1];
    const int row = rOff + blockIdx.x, tid = threadIdx.x;
    const int warp = tid >> 5, lane = tid & 31;

    float s = 0.f;
    for (int p = tid; p < NPART; p += 256) s += g_part[(size_t)row * NPART + p];
    red[tid] = s;
    __syncthreads();
    for (int o = 128; o > 0; o >>= 1) {
        if (tid < o) red[tid] += red[tid + o];
        __syncthreads();
    }
    if (tid == 0) {
        float iz = 0.5f / red[0];
        g_invZs[row] = iz;
        s_iz[0] = iz;
    }
    __syncthreads();

    const float iz = s_iz[0];
    const int cnt = g_fix_cnt[row];
    for (int slot = warp; slot < cnt; slot += 8) {
        int id = g_fix_id[row * N_ + slot];
        float dot = 0.f;
        for (int h = lane; h < H_; h += 32)
            dot += g_v[row * H_ + h] * mlp_w[(size_t)id * H_ + h];
#pragma unroll
        for (int o = 16; o > 0; o >>= 1) dot += __shfl_xor_sync(0xffffffffu, dot, o);
        if (lane == 0) {
            float sc = dot + mlp_b[id];
            g_fix_p[row * N_ + slot] =
                __logf(g_fix_p[row * N_ + slot] + iz * __expf(sc));
        }
    }
}

// ---------------- K4: finalize, 16 elems/thread (MLP 4), coalesced ----------------
__global__ void __launch_bounds__(256) k_finalize(float* __restrict__ out, int rOff) {
    const int row = rOff + blockIdx.y;
    const int tid = threadIdx.x;
    const int base4 = blockIdx.x * 1024;            // float4-group index within row
    const float pb = g_pbase[row], iz = g_invZs[row];
    const __half* src = g_sc + (size_t)row * E_;
    float* dst = out + (size_t)row * E_;

    uint2 p[4];
    int q4[4];
    bool ok[4];
#pragma unroll
    for (int j = 0; j < 4; j++) {
        q4[j] = base4 + j * 256 + tid;
        ok[j] = q4[j] < (E_ / 4);
        if (ok[j]) p[j] = __ldcs((const uint2*)(src + 4 * q4[j]));
    }
#pragma unroll
    for (int j = 0; j < 4; j++) {
        if (ok[j]) {
            __half2 h0 = *(__half2*)&p[j].x;
            __half2 h1 = *(__half2*)&p[j].y;
            float2 f0 = __half22float2(h0);
            float2 f1 = __half22float2(h1);
            float4 v;
            v.x = __logf(pb + iz * f0.x);
            v.y = __logf(pb + iz * f0.y);
            v.z = __logf(pb + iz * f1.x);
            v.w = __logf(pb + iz * f1.y);
            __stcs((float4*)(dst + 4 * q4[j]), v);
        }
    }
}

// ---------------- K5: write fixed values for history ids ----------------
__global__ void k_fix_post(float* __restrict__ out, int rOff) {
    const int row = rOff + blockIdx.x, t = threadIdx.x;
    if (t < g_fix_cnt[row]) {
        int id = g_fix_id[row * N_ + t];
        out[(size_t)row * E_ + id] = g_fix_p[row * N_ + t];
    }
}

// ---------------- launch: fork-join overlapped pipeline ----------------
extern "C" void kernel_launch(void* const* d_in, const int* in_sizes, int n_in,
                              void* d_out, int out_size) {
    const int*   idx   = (const int*)d_in[0];
    const int*   times = (const int*)d_in[1];
    const float* emb   = (const float*)d_in[2];
    const float* Ws_w  = (const float*)d_in[3];
    const float* Ws_b  = (const float*)d_in[4];
    const float* mlp_w = (const float*)d_in[5];
    const float* mlp_b = (const float*)d_in[6];
    float* out = (float*)d_out;

    static bool init_done = false;
    static cudaStream_t s2;
    static cudaEvent_t eFork, eConv, eGemmA, eGemmB;
    if (!init_done) {
        cudaFuncSetAttribute(k_proj, cudaFuncAttributeMaxDynamicSharedMemorySize, PROJ_SMEM);
        cudaFuncSetAttribute(k_gemm, cudaFuncAttributeMaxDynamicSharedMemorySize, GEMM_DSMEM);
        cudaStreamCreateWithFlags(&s2, cudaStreamNonBlocking);
        cudaEventCreateWithFlags(&eFork,  cudaEventDisableTiming);
        cudaEventCreateWithFlags(&eConv,  cudaEventDisableTiming);
        cudaEventCreateWithFlags(&eGemmA, cudaEventDisableTiming);
        cudaEventCreateWithFlags(&eGemmB, cudaEventDisableTiming);
        init_done = true;
    }

    // fork: convert on s2 overlaps proj+routing on main stream
    cudaEventRecord(eFork, 0);
    cudaStreamWaitEvent(s2, eFork, 0);
    k_convert<<<(E_ * 52 + 255) / 256, 256, 0, s2>>>(mlp_w);
    k_proj<<<(B_ * N_) / 128, 512, PROJ_SMEM>>>(idx, emb, Ws_w, Ws_b);
    k_routing<<<B_, 256>>>(idx, times);

    // gemmA (rows 0-255) on main stream after convert joins
    cudaEventRecord(eConv, s2);
    cudaStreamWaitEvent(0, eConv, 0);
    dim3 gg(RHALF / GBM, NPART);
    k_gemm<<<gg, 512, GEMM_DSMEM>>>(mlp_b, 0);
    cudaEventRecord(eGemmA, 0);

    // gemmB (rows 256-511) on s2, pipelined against A-half epilogue
    cudaStreamWaitEvent(s2, eGemmA, 0);
    k_gemm<<<gg, 512, GEMM_DSMEM, s2>>>(mlp_b, RHALF);
    cudaEventRecord(eGemmB, s2);

    // A-half epilogue on main stream (overlaps gemmB)
    k_reducefix<<<RHALF, 256>>>(mlp_w, mlp_b, 0);
    dim3 gf((E_ / 4 + 1023) / 1024, RHALF);
    k_finalize<<<gf, 256>>>(out, 0);
    k_fix_post<<<RHALF, 64>>>(out, 0);

    // join, then B-half epilogue
    cudaStreamWaitEvent(0, eGemmB, 0);
    k_reducefix<<<RHALF, 256>>>(mlp_w, mlp_b, RHALF);
    k_finalize<<<gf, 256>>>(out, RHALF);
    k_fix_post<<<RHALF, 64>>>(out, RHALF);
}

// round 15
// speedup vs baseline: 1.1623x; 1.1623x over previous
#include <cuda_runtime.h>
#include <cuda_bf16.h>
#include <cuda_fp16.h>
#include <cstdint>

#define B_    512
#define N_    50
#define D_    128
#define H_    200
#define E_    50000
#define EPAD  50048         // 391*128 — padded entity rows (zero-init tail)
#define KPAD  208           // H_ padded to 13*16 for decoder mma
#define GBM   128
#define GBN   128
#define NPART 391           // EPAD/GBN
#define SAS   216           // decoder gemm smem stride (bf16 elems)
#define PSTR  136           // projection gemm smem stride (bf16)

// ---------------- static device scratch ----------------
__device__ __nv_bfloat16 g_wb[(size_t)EPAD * KPAD];    // mlp_w bf16, padded (tail zero)
__device__ __align__(16) __half g_sc[(size_t)B_ * E_]; // fp16 exp(score) (51.2 MB)
__device__ __align__(16) float g_x[(size_t)B_ * N_ * H_]; // projected x (20.5 MB)
__device__ __nv_bfloat16 g_vb[B_ * KPAD];              // poses bf16, K-padded
__device__ float g_v[B_ * H_];                         // poses fp32 (for fixdot)
__device__ float g_part[(size_t)B_ * NPART];           // per-(row, e-block) exp partials
__device__ float g_invZs[B_];                          // 0.5 / Z_s
__device__ float g_pbase[B_];                          // 0.5 * exp(-m_p) / Z_p
__device__ float g_fix_p[B_ * N_];
__device__ int   g_fix_id[B_ * N_];
__device__ int   g_fix_cnt[B_];

// ---------------- shared PTX helpers ----------------
__device__ __forceinline__ uint32_t smem_u32(const void* p) {
    uint32_t a;
    asm("{ .reg .u64 t; cvta.to.shared.u64 t, %1; cvt.u32.u64 %0, t; }" : "=r"(a) : "l"(p));
    return a;
}
__device__ __forceinline__ void mma16816(float* c, const unsigned* a, const unsigned* b) {
    asm volatile("mma.sync.aligned.m16n8k16.row.col.f32.bf16.bf16.f32 "
        "{%0,%1,%2,%3}, {%4,%5,%6,%7}, {%8,%9}, {%0,%1,%2,%3};"
        : "+f"(c[0]), "+f"(c[1]), "+f"(c[2]), "+f"(c[3])
        : "r"(a[0]), "r"(a[1]), "r"(a[2]), "r"(a[3]), "r"(b[0]), "r"(b[1]));
}
__device__ __forceinline__ void ldsm_x4(unsigned* r, uint32_t addr) {
    asm volatile("ldmatrix.sync.aligned.m8n8.x4.shared.b16 {%0,%1,%2,%3}, [%4];"
        : "=r"(r[0]), "=r"(r[1]), "=r"(r[2]), "=r"(r[3]) : "r"(addr));
}
__device__ __forceinline__ void cp16(uint32_t dst, const void* src) {
    asm volatile("cp.async.cg.shared.global [%0], [%1], 16;" :: "r"(dst), "l"(src));
}
#define CP_COMMIT() asm volatile("cp.async.commit_group;")
#define CP_WAIT0()  asm volatile("cp.async.wait_group 0;" ::: "memory")

// ---------------- K0: mlp_w fp32 -> bf16 padded ----------------
__global__ void k_convert(const float* __restrict__ w) {
    int i = blockIdx.x * 256 + threadIdx.x;        // uint2 (4 bf16) index
    if (i >= E_ * 52) return;
    int e = i / 52, q = i % 52;
    uint2 val;
    if (q < 50) {
        float4 f = *(const float4*)(w + (size_t)e * H_ + 4 * q);
        __nv_bfloat162 lo = __floats2bfloat162_rn(f.x, f.y);
        __nv_bfloat162 hi = __floats2bfloat162_rn(f.z, f.w);
        val.x = *(unsigned*)&lo;
        val.y = *(unsigned*)&hi;
    } else {
        val.x = 0u; val.y = 0u;
    }
    ((uint2*)g_wb)[(size_t)e * 52 + q] = val;
}

// ---------------- K-proj: X = gather(embeds) @ Ws^T + b   (bf16 mma) ----------------
#define PROJ_SMEM ((128 * PSTR + 224 * PSTR) * 2 + 224 * 4)

__global__ void __launch_bounds__(512) k_proj(
    const int* __restrict__ idx, const float* __restrict__ emb,
    const float* __restrict__ Ws_w, const float* __restrict__ Ws_b)
{
    extern __shared__ __align__(16) char psm[];
    __nv_bfloat16* sA = (__nv_bfloat16*)psm;          // [128][PSTR]
    __nv_bfloat16* sB = sA + 128 * PSTR;              // [224][PSTR]
    float* sBias = (float*)(sB + 224 * PSTR);         // [224]

    const int tid = threadIdx.x;
    const int m0 = blockIdx.x * 128;

    if (tid < 224) sBias[tid] = (tid < H_) ? Ws_b[tid] : 0.f;
    for (int i = tid; i < 128 * 32; i += 512) {
        int r = i >> 5, c4 = i & 31;
        int e = idx[m0 + r];
        float4 f = *(const float4*)(emb + (size_t)e * D_ + 4 * c4);
        __nv_bfloat162 lo = __floats2bfloat162_rn(f.x, f.y);
        __nv_bfloat162 hi = __floats2bfloat162_rn(f.z, f.w);
        uint2 v; v.x = *(unsigned*)&lo; v.y = *(unsigned*)&hi;
        ((uint2*)(sA + r * PSTR))[c4] = v;
    }
    for (int i = tid; i < 200 * 32; i += 512) {
        int r = i >> 5, c4 = i & 31;
        float4 f = *(const float4*)(Ws_w + r * D_ + 4 * c4);
        __nv_bfloat162 lo = __floats2bfloat162_rn(f.x, f.y);
        __nv_bfloat162 hi = __floats2bfloat162_rn(f.z, f.w);
        uint2 v; v.x = *(unsigned*)&lo; v.y = *(unsigned*)&hi;
        ((uint2*)(sB + r * PSTR))[c4] = v;
    }
    __syncthreads();

    const int lane = tid & 31, warp = tid >> 5;
    const int gid = lane >> 2, tig = lane & 3;
    const int wm = warp & 7, wn = warp >> 3;

    const uint32_t sA_u = smem_u32(sA), sB_u = smem_u32(sB);
    const uint32_t aAddr = sA_u + (uint32_t)(((wm * 16 + (lane & 15)) * PSTR + (lane >> 4) * 8) * 2);
    uint32_t bAddr[7];
#pragma unroll
    for (int j = 0; j < 7; j++)
        bAddr[j] = sB_u + (uint32_t)(((wn * 112 + j * 16 + (lane & 7) + ((lane >> 4) & 1) * 8) * PSTR
                                     + ((lane >> 3) & 1) * 8) * 2);

    float acc[14][4];
#pragma unroll
    for (int ni = 0; ni < 14; ni++)
#pragma unroll
        for (int q = 0; q < 4; q++) acc[ni][q] = 0.f;

#pragma unroll
    for (int ks = 0; ks < 8; ks++) {
        const uint32_t koff = ks * 32u;
        unsigned a[4];
        ldsm_x4(a, aAddr + koff);
#pragma unroll
        for (int j = 0; j < 7; j++) {
            unsigned bb[4];
            ldsm_x4(bb, bAddr[j] + koff);
            mma16816(acc[2 * j],     a, bb + 0);
            mma16816(acc[2 * j + 1], a, bb + 2);
        }
    }

    const int r0 = m0 + wm * 16 + gid;
#pragma unroll
    for (int ni = 0; ni < 14; ni++) {
        int c = wn * 112 + ni * 8 + 2 * tig;
        if (c < H_) {
            float b0 = sBias[c], b1 = sBias[c + 1];
            float2 v0, v1;
            v0.x = acc[ni][0] + b0; v0.y = acc[ni][1] + b1;
            v1.x = acc[ni][2] + b0; v1.y = acc[ni][3] + b1;
            *(float2*)(g_x + (size_t)r0 * H_ + c)       = v0;
            *(float2*)(g_x + (size_t)(r0 + 8) * H_ + c) = v1;
        }
    }
}

// ---------------- K1: routing (256 thr, fused gather+normalize) ----------------
__global__ void __launch_bounds__(256, 4) k_routing(
    const int* __restrict__ idx, const int* __restrict__ times)
{
    __shared__ __align__(16) float sU[50 * 200];
    __shared__ float sB[50], sC[50], sV[200], sTmp[50], sRed[8];
    __shared__ int   sIdx[50];

    const int tid = threadIdx.x;
    const int lane = tid & 31, wid = tid >> 5;   // 8 warps
    const int row = blockIdx.x;

    if (tid < 50) {
        sIdx[tid] = idx[row * N_ + tid];
        sB[tid] = 2.0f / (1.0f + (float)times[row * N_ + tid]);
    }

    for (int n = wid; n < 50; n += 8) {
        const float4* src = (const float4*)(g_x + ((size_t)row * N_ + n) * H_);
        float4 f0 = src[lane];
        float ss = f0.x * f0.x + f0.y * f0.y + f0.z * f0.z + f0.w * f0.w;
        float4 f1;
        const bool has2 = lane < 18;
        if (has2) {
            f1 = src[32 + lane];
            ss += f1.x * f1.x + f1.y * f1.y + f1.z * f1.z + f1.w * f1.w;
        }
#pragma unroll
        for (int o = 16; o > 0; o >>= 1) ss += __shfl_xor_sync(0xffffffffu, ss, o);
        float inv = 1.0f / fmaxf(sqrtf(ss), 1e-12f);
        float4* dst = (float4*)(sU + n * 200);
        f0.x *= inv; f0.y *= inv; f0.z *= inv; f0.w *= inv;
        dst[lane] = f0;
        if (has2) {
            f1.x *= inv; f1.y *= inv; f1.z *= inv; f1.w *= inv;
            dst[32 + lane] = f1;
        }
    }
    __syncthreads();

    for (int r = 0; r < 3; r++) {
        if (wid == 0) {
            float v0 = (lane < 50) ? sB[lane] : -1e30f;
            float v1 = (lane + 32 < 50) ? sB[lane + 32] : -1e30f;
            float m = fmaxf(v0, v1);
#pragma unroll
            for (int o = 16; o > 0; o >>= 1) m = fmaxf(m, __shfl_xor_sync(0xffffffffu, m, o));
            float e0 = (lane < 50) ? expf(v0 - m) : 0.f;
            float e1 = (lane + 32 < 50) ? expf(v1 - m) : 0.f;
            float s = e0 + e1;
#pragma unroll
            for (int o = 16; o > 0; o >>= 1) s += __shfl_xor_sync(0xffffffffu, s, o);
            float sc = 50.0f / s;
            if (lane < 50) sC[lane] = e0 * sc;
            if (lane + 32 < 50) sC[lane + 32] = e1 * sc;
        }
        __syncthreads();

        float sv = 0.f, mysq = 0.f;
        if (tid < H_) {
#pragma unroll 5
            for (int n = 0; n < 50; n++) sv += sC[n] * sU[n * H_ + tid];
            mysq = sv * sv;
        }
#pragma unroll
        for (int o = 16; o > 0; o >>= 1) mysq += __shfl_xor_sync(0xffffffffu, mysq, o);
        if (lane == 0) sRed[wid] = mysq;
        __syncthreads();

        float sq = 0.f;
#pragma unroll
        for (int i = 0; i < 8; i++) sq += sRed[i];
        float scale = sq / ((1.0f + sq) * sqrtf(sq + 1e-9f));
        if (tid < H_) sV[tid] = sv * scale;
        __syncthreads();

        if (r < 2) {
            for (int n = wid; n < 50; n += 8) {
                float dot = 0.f;
                for (int h = lane; h < H_; h += 32) dot += sU[n * H_ + h] * sV[h];
#pragma unroll
                for (int o = 16; o > 0; o >>= 1) dot += __shfl_xor_sync(0xffffffffu, dot, o);
                if (lane == 0) sB[n] += dot;
            }
            __syncthreads();
        }
    }

    if (tid < H_) {
        float v = sV[tid];
        g_v[row * H_ + tid] = v;
        g_vb[row * KPAD + tid] = __float2bfloat16(v);
    } else if (tid < KPAD) {
        g_vb[row * KPAD + tid] = __float2bfloat16(0.f);
    }

    if (tid < 50) {
        int my = sIdx[tid];
        bool first = true;
        float cs = 0.f;
        for (int m = 0; m < 50; m++) {
            if (sIdx[m] == my) {
                cs += sC[m];
                if (m < tid) first = false;
            }
        }
        sTmp[tid] = first ? cs : -1.0f;
    }
    __syncthreads();
    if (tid == 0) {
        float mp = -1e30f; int K = 0;
        for (int n = 0; n < 50; n++)
            if (sTmp[n] >= 0.f) { K++; mp = fmaxf(mp, sTmp[n]); }
        float Zp = (float)(E_ - K) * expf(-mp);
        for (int n = 0; n < 50; n++)
            if (sTmp[n] >= 0.f) Zp += expf(sTmp[n] - mp);
        int slot = 0;
        for (int n = 0; n < 50; n++)
            if (sTmp[n] >= 0.f) {
                g_fix_id[row * N_ + slot] = sIdx[n];
                g_fix_p[row * N_ + slot] = 0.5f * expf(sTmp[n] - mp) / Zp;
                slot++;
            }
        g_fix_cnt[row] = K;
        g_pbase[row] = 0.5f * expf(-mp) / Zp;
    }
}

// ---------------- K2: decoder GEMM 128x128, stores exp(score) as half ----------------
#define GEMM_DSMEM ((GBM + GBN) * SAS * 2 + 512)

__global__ void __launch_bounds__(512) k_gemm(const float* __restrict__ mlp_b)
{
    extern __shared__ __align__(16) char gsm[];
    __nv_bfloat16* sA   = (__nv_bfloat16*)gsm;
    __nv_bfloat16* sBm  = sA + GBM * SAS;
    float*         sBias= (float*)(sBm + GBN * SAS);
    float (*s_part)[16] = (float (*)[16])gsm;

    const int tid = threadIdx.x;
    const int rBase = blockIdx.x * GBM;    // 4 r-tiles fastest -> weight tile L2 reuse
    const int eBase = blockIdx.y * GBN;

    if (tid < GBN) {
        int e = eBase + tid;
        sBias[tid] = (e < E_) ? mlp_b[e] : 0.f;
    }
    {
        const uint32_t sA_b = smem_u32(sA), sB_b = smem_u32(sBm);
        const char* srcA = (const char*)g_vb + (size_t)rBase * KPAD * 2;
        const char* srcB = (const char*)g_wb + (size_t)eBase * KPAD * 2;
        for (int i = tid; i < GBM * 26; i += 512) {
            int r = i / 26, c = i - r * 26;
            cp16(sA_b + (uint32_t)(r * (SAS * 2) + c * 16), srcA + (size_t)r * 416 + c * 16);
        }
        for (int i = tid; i < GBN * 26; i += 512) {
            int r = i / 26, c = i - r * 26;
            cp16(sB_b + (uint32_t)(r * (SAS * 2) + c * 16), srcB + (size_t)r * 416 + c * 16);
        }
        CP_COMMIT();
        CP_WAIT0();
    }
    __syncthreads();

    const int lane = tid & 31, warp = tid >> 5;
    const int gid = lane >> 2, tig = lane & 3;
    const int wm = warp & 3, wn = warp >> 2;

    const uint32_t sA_u = smem_u32(sA), sB_u = smem_u32(sBm);
    uint32_t aAddr0 = sA_u + (uint32_t)(((wm * 32 + (lane & 15)) * SAS + ((lane >> 4) * 8)) * 2);
    uint32_t aAddr1 = aAddr0 + 16u * SAS * 2u;
    uint32_t bAddr0 = sB_u + (uint32_t)(((wn * 32 + (lane & 7) + (((lane >> 4) & 1) * 8)) * SAS
                                        + (((lane >> 3) & 1) * 8)) * 2);
    uint32_t bAddr1 = bAddr0 + 16u * SAS * 2u;

    float acc[2][4][4];
#pragma unroll
    for (int mi = 0; mi < 2; mi++)
#pragma unroll
        for (int ni = 0; ni < 4; ni++)
#pragma unroll
            for (int q = 0; q < 4; q++) acc[mi][ni][q] = 0.f;

#pragma unroll
    for (int ks = 0; ks < 13; ks++) {
        const uint32_t koff = ks * 32u;
        unsigned a0[4], a1[4], b0[4], b1[4];
        ldsm_x4(a0, aAddr0 + koff);
        ldsm_x4(a1, aAddr1 + koff);
        ldsm_x4(b0, bAddr0 + koff);
        ldsm_x4(b1, bAddr1 + koff);
        mma16816(acc[0][0], a0, b0 + 0);
        mma16816(acc[0][1], a0, b0 + 2);
        mma16816(acc[0][2], a0, b1 + 0);
        mma16816(acc[0][3], a0, b1 + 2);
        mma16816(acc[1][0], a1, b0 + 0);
        mma16816(acc[1][1], a1, b0 + 2);
        mma16816(acc[1][2], a1, b1 + 0);
        mma16816(acc[1][3], a1, b1 + 2);
    }

    float rs[2][2] = {{0.f, 0.f}, {0.f, 0.f}};
#pragma unroll
    for (int mi = 0; mi < 2; mi++) {
        int r0 = rBase + wm * 32 + mi * 16 + gid;
#pragma unroll
        for (int ni = 0; ni < 4; ni++) {
            int ec = wn * 32 + ni * 8 + 2 * tig;
            int e0 = eBase + ec;
            if (e0 < E_) {
                float b0 = sBias[ec], b1 = sBias[ec + 1];
                float E00 = __expf(acc[mi][ni][0] + b0);
                float E01 = __expf(acc[mi][ni][1] + b1);
                float E10 = __expf(acc[mi][ni][2] + b0);
                float E11 = __expf(acc[mi][ni][3] + b1);
                *(__half2*)(g_sc + (size_t)r0 * E_ + e0)       = __floats2half2_rn(E00, E01);
                *(__half2*)(g_sc + (size_t)(r0 + 8) * E_ + e0) = __floats2half2_rn(E10, E11);
                rs[mi][0] += E00 + E01;
                rs[mi][1] += E10 + E11;
            }
        }
    }
    __syncthreads();   // sA dead -> safe to alias as s_part
    const int slot = wn * 4 + tig;
#pragma unroll
    for (int mi = 0; mi < 2; mi++) {
        s_part[wm * 32 + mi * 16 + gid][slot]     = rs[mi][0];
        s_part[wm * 32 + mi * 16 + gid + 8][slot] = rs[mi][1];
    }
    __syncthreads();
    if (tid < GBM) {
        float s = 0.f;
#pragma unroll
        for (int j = 0; j < 16; j++) s += s_part[tid][j];
        g_part[(size_t)(rBase + tid) * NPART + blockIdx.y] = s;
    }
}

// ---------------- K3: fused reduce (0.5/Z_s) + fixdot (block per row) ----------------
__global__ void __launch_bounds__(256) k_reducefix(const float* __restrict__ mlp_w,
                                                   const float* __restrict__ mlp_b) {
    __shared__ float red[256];
    __shared__ float s_iz[1];
    const int row = blockIdx.x, tid = threadIdx.x;
    const int warp = tid >> 5, lane = tid & 31;

    float s = 0.f;
    for (int p = tid; p < NPART; p += 256) s += g_part[(size_t)row * NPART + p];
    red[tid] = s;
    __syncthreads();
    for (int o = 128; o > 0; o >>= 1) {
        if (tid < o) red[tid] += red[tid + o];
        __syncthreads();
    }
    if (tid == 0) {
        float iz = 0.5f / red[0];
        g_invZs[row] = iz;
        s_iz[0] = iz;
    }
    __syncthreads();

    const float iz = s_iz[0];
    const int cnt = g_fix_cnt[row];
    for (int slot = warp; slot < cnt; slot += 8) {
        int id = g_fix_id[row * N_ + slot];
        float dot = 0.f;
        for (int h = lane; h < H_; h += 32)
            dot += g_v[row * H_ + h] * mlp_w[(size_t)id * H_ + h];
#pragma unroll
        for (int o = 16; o > 0; o >>= 1) dot += __shfl_xor_sync(0xffffffffu, dot, o);
        if (lane == 0) {
            float sc = dot + mlp_b[id];
            g_fix_p[row * N_ + slot] =
                __logf(g_fix_p[row * N_ + slot] + iz * __expf(sc));
        }
    }
}

// ---------------- K4: finalize, 16 elems/thread (MLP 4), coalesced ----------------
__global__ void __launch_bounds__(256) k_finalize(float* __restrict__ out) {
    const int row = blockIdx.y;
    const int tid = threadIdx.x;
    const int base4 = blockIdx.x * 1024;            // float4-group index within row
    const float pb = g_pbase[row], iz = g_invZs[row];
    const __half* src = g_sc + (size_t)row * E_;
    float* dst = out + (size_t)row * E_;

    uint2 p[4];
    int q4[4];
    bool ok[4];
#pragma unroll
    for (int j = 0; j < 4; j++) {
        q4[j] = base4 + j * 256 + tid;
        ok[j] = q4[j] < (E_ / 4);
        if (ok[j]) p[j] = __ldcs((const uint2*)(src + 4 * q4[j]));
    }
#pragma unroll
    for (int j = 0; j < 4; j++) {
        if (ok[j]) {
            __half2 h0 = *(__half2*)&p[j].x;
            __half2 h1 = *(__half2*)&p[j].y;
            float2 f0 = __half22float2(h0);
            float2 f1 = __half22float2(h1);
            float4 v;
            v.x = __logf(pb + iz * f0.x);
            v.y = __logf(pb + iz * f0.y);
            v.z = __logf(pb + iz * f1.x);
            v.w = __logf(pb + iz * f1.y);
            __stcs((float4*)(dst + 4 * q4[j]), v);
        }
    }
}

// ---------------- K5: write fixed values for history ids ----------------
__global__ void k_fix_post(float* __restrict__ out) {
    const int row = blockIdx.x, t = threadIdx.x;
    if (t < g_fix_cnt[row]) {
        int id = g_fix_id[row * N_ + t];
        out[(size_t)row * E_ + id] = g_fix_p[row * N_ + t];
    }
}

// ---------------- launch: R13 structure + convert-only side-stream overlap ----------------
extern "C" void kernel_launch(void* const* d_in, const int* in_sizes, int n_in,
                              void* d_out, int out_size) {
    const int*   idx   = (const int*)d_in[0];
    const int*   times = (const int*)d_in[1];
    const float* emb   = (const float*)d_in[2];
    const float* Ws_w  = (const float*)d_in[3];
    const float* Ws_b  = (const float*)d_in[4];
    const float* mlp_w = (const float*)d_in[5];
    const float* mlp_b = (const float*)d_in[6];
    float* out = (float*)d_out;

    static bool init_done = false;
    static cudaStream_t s2;
    static cudaEvent_t eFork, eConv;
    if (!init_done) {
        cudaFuncSetAttribute(k_proj, cudaFuncAttributeMaxDynamicSharedMemorySize, PROJ_SMEM);
        cudaFuncSetAttribute(k_gemm, cudaFuncAttributeMaxDynamicSharedMemorySize, GEMM_DSMEM);
        cudaStreamCreateWithFlags(&s2, cudaStreamNonBlocking);
        cudaEventCreateWithFlags(&eFork, cudaEventDisableTiming);
        cudaEventCreateWithFlags(&eConv, cudaEventDisableTiming);
        init_done = true;
    }

    // fork: convert on s2 overlaps proj+routing on main stream; join before gemm
    cudaEventRecord(eFork, 0);
    cudaStreamWaitEvent(s2, eFork, 0);
    k_convert<<<(E_ * 52 + 255) / 256, 256, 0, s2>>>(mlp_w);
    cudaEventRecord(eConv, s2);

    k_proj<<<(B_ * N_) / 128, 512, PROJ_SMEM>>>(idx, emb, Ws_w, Ws_b);
    k_routing<<<B_, 256>>>(idx, times);

    cudaStreamWaitEvent(0, eConv, 0);
    dim3 gg(B_ / GBM, NPART);
    k_gemm<<<gg, 512, GEMM_DSMEM>>>(mlp_b);
    k_reducefix<<<B_, 256>>>(mlp_w, mlp_b);
    dim3 gf((E_ / 4 + 1023) / 1024, B_);
    k_finalize<<<gf, 256>>>(out);
    k_fix_post<<<B_, 64>>>(out);
}